// round 6
// baseline (speedup 1.0000x reference)
#include <cuda_runtime.h>
#include <cuda_fp16.h>

#define NN   50000
#define EE   800000
#define HID  128
#define BK   64          // padded bucket width (max degree incl. self-loop ~40)

// ---------------- device scratch (no allocations allowed) ----------------
__device__ float  d_h1[NN * HID];    // x @ W1 (fp32)
__device__ float  d_t1[NN * HID];    // relu(layer1 out)
__device__ float  d_h2[NN * HID];    // t1 @ W2 (fp32)
__device__ __half d_hh[NN * HID];    // fp16 gather copy of current layer's h
__device__ float  d_al[NN];
__device__ float  d_ar[NN];
__device__ int    d_srcPad[NN * BK]; // padded per-dst source buckets
__device__ int    d_fill[NN];        // per-dst degree (incl. self-loop)
__device__ float  d_p[NN * 8];       // per-node [p_src(4), p_dst(4)]

// ---------------- packed f32x2 helpers (sm_100+ FFMA2 path) ----------------
__device__ __forceinline__ unsigned long long pack2(float lo, float hi) {
    unsigned long long r;
    asm("mov.b64 %0,{%1,%2};" : "=l"(r) : "f"(lo), "f"(hi));
    return r;
}
__device__ __forceinline__ unsigned long long fma2(unsigned long long a,
                                                   unsigned long long b,
                                                   unsigned long long c) {
    unsigned long long d;
    asm("fma.rn.f32x2 %0,%1,%2,%3;" : "=l"(d) : "l"(a), "l"(b), "l"(c));
    return d;
}
__device__ __forceinline__ void unpack2(unsigned long long v, float& lo, float& hi) {
    asm("mov.b64 {%0,%1},%2;" : "=f"(lo), "=f"(hi) : "l"(v));
}

// ---------------- scan-free CSR: padded bucket scatter ----------------
__global__ void k_place1(const int* __restrict__ ei) {
    int e = blockIdx.x * blockDim.x + threadIdx.x;
    if (e >= EE) return;
    int c = ei[EE + e];
    int pos = atomicAdd(&d_fill[c], 1);
    if (pos < BK) d_srcPad[c * BK + pos] = ei[e];
}
__global__ void k_place2() {
    int n = blockIdx.x * blockDim.x + threadIdx.x;
    if (n >= NN) return;
    int pos = atomicAdd(&d_fill[n], 1);
    if (pos < BK) d_srcPad[n * BK + pos] = n;
}

// ---------------- GEMM: C[M,128] = A[M,128] @ B[128,128], fp32 via FFMA2 ----------------
// block tile 128x128, thread tile 8x8 (cols tc*4 and 64+tc*4), 256 threads.
// Fused epilogue: att_l/att_r dots + fp16 copy of C into d_hh.
__global__ void __launch_bounds__(256) k_gemm(const float* __restrict__ Aext,
                                              const float* __restrict__ B,
                                              const float* __restrict__ attl,
                                              const float* __restrict__ attr,
                                              int selA, int selC) {
    const float* A = selA ? d_t1 : Aext;
    float* C = selC ? d_h2 : d_h1;

    __shared__ float As[16][132];
    __shared__ float Bs[16][128];

    int tid = threadIdx.x;
    int tr = tid >> 4, tc = tid & 15;
    int mBase = blockIdx.x * 128;
    int c0 = tc * 4;
    int c1 = 64 + tc * 4;

    unsigned long long acc[8][4];
    unsigned long long z = pack2(0.f, 0.f);
    #pragma unroll
    for (int i = 0; i < 8; i++)
        #pragma unroll
        for (int p = 0; p < 4; p++) acc[i][p] = z;

    for (int kc = 0; kc < 128; kc += 16) {
        #pragma unroll
        for (int l = 0; l < 2; l++) {
            int f = tid + l * 256;
            int r = f >> 2, cg = (f & 3) << 2;
            float4 v = make_float4(0.f, 0.f, 0.f, 0.f);
            int gr = mBase + r;
            if (gr < NN) v = *reinterpret_cast<const float4*>(A + (size_t)gr * HID + kc + cg);
            As[cg + 0][r] = v.x; As[cg + 1][r] = v.y; As[cg + 2][r] = v.z; As[cg + 3][r] = v.w;
            int k = f >> 5, n4 = (f & 31) << 2;
            *reinterpret_cast<float4*>(&Bs[k][n4]) =
                *reinterpret_cast<const float4*>(B + (size_t)(kc + k) * HID + n4);
        }
        __syncthreads();
        #pragma unroll
        for (int kk = 0; kk < 16; kk++) {
            float4 a0 = *reinterpret_cast<const float4*>(&As[kk][tr * 8]);
            float4 a1 = *reinterpret_cast<const float4*>(&As[kk][tr * 8 + 4]);
            float4 b0 = *reinterpret_cast<const float4*>(&Bs[kk][c0]);
            float4 b1 = *reinterpret_cast<const float4*>(&Bs[kk][c1]);
            unsigned long long pb[4];
            pb[0] = pack2(b0.x, b0.y); pb[1] = pack2(b0.z, b0.w);
            pb[2] = pack2(b1.x, b1.y); pb[3] = pack2(b1.z, b1.w);
            float av[8] = {a0.x, a0.y, a0.z, a0.w, a1.x, a1.y, a1.z, a1.w};
            #pragma unroll
            for (int i = 0; i < 8; i++) {
                unsigned long long ad = pack2(av[i], av[i]);
                #pragma unroll
                for (int p = 0; p < 4; p++) acc[i][p] = fma2(ad, pb[p], acc[i][p]);
            }
        }
        __syncthreads();
    }

    float alv[8], arv[8];
    #pragma unroll
    for (int j = 0; j < 4; j++) {
        alv[j]     = attl[c0 + j]; arv[j]     = attr[c0 + j];
        alv[4 + j] = attl[c1 + j]; arv[4 + j] = attr[c1 + j];
    }

    #pragma unroll
    for (int i = 0; i < 8; i++) {
        int gr = mBase + tr * 8 + i;
        float cv[8];
        unpack2(acc[i][0], cv[0], cv[1]); unpack2(acc[i][1], cv[2], cv[3]);
        unpack2(acc[i][2], cv[4], cv[5]); unpack2(acc[i][3], cv[6], cv[7]);
        float pl = 0.f, pr = 0.f;
        #pragma unroll
        for (int j = 0; j < 8; j++) { pl += cv[j] * alv[j]; pr += cv[j] * arv[j]; }
        #pragma unroll
        for (int off = 8; off; off >>= 1) {
            pl += __shfl_xor_sync(0xffffffffu, pl, off);
            pr += __shfl_xor_sync(0xffffffffu, pr, off);
        }
        if (gr < NN) {
            *reinterpret_cast<float4*>(C + (size_t)gr * HID + c0) =
                make_float4(cv[0], cv[1], cv[2], cv[3]);
            *reinterpret_cast<float4*>(C + (size_t)gr * HID + c1) =
                make_float4(cv[4], cv[5], cv[6], cv[7]);
            // fp16 gather copy
            __half2 p01 = __floats2half2_rn(cv[0], cv[1]);
            __half2 p23 = __floats2half2_rn(cv[2], cv[3]);
            __half2 p45 = __floats2half2_rn(cv[4], cv[5]);
            __half2 p67 = __floats2half2_rn(cv[6], cv[7]);
            uint2 u0, u1;
            u0.x = *reinterpret_cast<unsigned*>(&p01); u0.y = *reinterpret_cast<unsigned*>(&p23);
            u1.x = *reinterpret_cast<unsigned*>(&p45); u1.y = *reinterpret_cast<unsigned*>(&p67);
            *reinterpret_cast<uint2*>(d_hh + (size_t)gr * HID + c0) = u0;
            *reinterpret_cast<uint2*>(d_hh + (size_t)gr * HID + c1) = u1;
            if (tc == 0) { d_al[gr] = pl; d_ar[gr] = pr; }
        }
    }
}

// ---------------- fused SuperGAT attention, ONLINE softmax, fp16 gathers ----------------
__global__ void k_attn(int selH, const float* __restrict__ bias, int doRelu,
                       int doProj, const float* __restrict__ Wc) {
    int gw = (blockIdx.x * blockDim.x + threadIdx.x) >> 5;
    if (gw >= NN) return;
    int lane = threadIdx.x & 31;
    const float* h = selH ? d_h2 : d_h1;

    float4 hd = reinterpret_cast<const float4*>(h + (size_t)gw * HID)[lane];
    float ard = d_ar[gw];
    int base = gw * BK;
    int deg = d_fill[gw];
    if (deg > BK) deg = BK;

    float m = -1e30f, ss = 0.f;
    float4 acc = make_float4(0.f, 0.f, 0.f, 0.f);

    int i = 0;
    for (; i + 3 < deg; i += 4) {
        int s[4]; float alv[4]; float p[4];
        float2 f01[4], f23[4];
        #pragma unroll
        for (int j = 0; j < 4; j++) s[j] = d_srcPad[base + i + j];
        #pragma unroll
        for (int j = 0; j < 4; j++) {
            alv[j] = d_al[s[j]];
            uint2 raw = reinterpret_cast<const uint2*>(d_hh + (size_t)s[j] * HID)[lane];
            f01[j] = __half22float2(*reinterpret_cast<__half2*>(&raw.x));
            f23[j] = __half22float2(*reinterpret_cast<__half2*>(&raw.y));
        }
        #pragma unroll
        for (int j = 0; j < 4; j++)
            p[j] = hd.x * f01[j].x + hd.y * f01[j].y + hd.z * f23[j].x + hd.w * f23[j].y;
        #pragma unroll
        for (int off = 16; off; off >>= 1) {
            #pragma unroll
            for (int j = 0; j < 4; j++)
                p[j] += __shfl_xor_sync(0xffffffffu, p[j], off);
        }
        float a[4], mn = m;
        #pragma unroll
        for (int j = 0; j < 4; j++) {
            a[j] = (alv[j] + ard) * (1.0f / (1.0f + __expf(-p[j])));
            mn = fmaxf(mn, a[j]);
        }
        float sc = __expf(m - mn);
        float e[4];
        #pragma unroll
        for (int j = 0; j < 4; j++) e[j] = __expf(a[j] - mn);
        acc.x = acc.x * sc + e[0] * f01[0].x + e[1] * f01[1].x + e[2] * f01[2].x + e[3] * f01[3].x;
        acc.y = acc.y * sc + e[0] * f01[0].y + e[1] * f01[1].y + e[2] * f01[2].y + e[3] * f01[3].y;
        acc.z = acc.z * sc + e[0] * f23[0].x + e[1] * f23[1].x + e[2] * f23[2].x + e[3] * f23[3].x;
        acc.w = acc.w * sc + e[0] * f23[0].y + e[1] * f23[1].y + e[2] * f23[2].y + e[3] * f23[3].y;
        ss = ss * sc + e[0] + e[1] + e[2] + e[3];
        m = mn;
    }
    for (; i < deg; i++) {
        int s0 = d_srcPad[base + i];
        float al0 = d_al[s0];
        uint2 raw = reinterpret_cast<const uint2*>(d_hh + (size_t)s0 * HID)[lane];
        float2 f01 = __half22float2(*reinterpret_cast<__half2*>(&raw.x));
        float2 f23 = __half22float2(*reinterpret_cast<__half2*>(&raw.y));
        float p0 = hd.x * f01.x + hd.y * f01.y + hd.z * f23.x + hd.w * f23.y;
        #pragma unroll
        for (int off = 16; off; off >>= 1) p0 += __shfl_xor_sync(0xffffffffu, p0, off);
        float a0 = (al0 + ard) * (1.0f / (1.0f + __expf(-p0)));
        float mn = fmaxf(m, a0);
        float sc = __expf(m - mn);
        float e0 = __expf(a0 - mn);
        acc.x = acc.x * sc + e0 * f01.x;
        acc.y = acc.y * sc + e0 * f01.y;
        acc.z = acc.z * sc + e0 * f23.x;
        acc.w = acc.w * sc + e0 * f23.y;
        ss = ss * sc + e0;
        m = mn;
    }

    float inv = 1.0f / (ss + 1e-16f);
    float4 bv = reinterpret_cast<const float4*>(bias)[lane];
    float4 o = make_float4(acc.x * inv + bv.x, acc.y * inv + bv.y,
                           acc.z * inv + bv.z, acc.w * inv + bv.w);
    if (doRelu) {
        o.x = fmaxf(o.x, 0.f); o.y = fmaxf(o.y, 0.f);
        o.z = fmaxf(o.z, 0.f); o.w = fmaxf(o.w, 0.f);
    }

    if (!doProj) {
        reinterpret_cast<float4*>(d_t1 + (size_t)gw * HID)[lane] = o;
        return;
    }

    // fused classifier partials
    const float4* WcV = reinterpret_cast<const float4*>(Wc);
    int k0 = lane * 4;
    float hj[4] = {o.x, o.y, o.z, o.w};
    float4 as = make_float4(0.f, 0.f, 0.f, 0.f);
    float4 ad = make_float4(0.f, 0.f, 0.f, 0.f);
    #pragma unroll
    for (int j = 0; j < 4; j++) {
        float4 w = WcV[k0 + j];
        as.x += hj[j] * w.x; as.y += hj[j] * w.y; as.z += hj[j] * w.z; as.w += hj[j] * w.w;
        float4 w2 = WcV[128 + k0 + j];
        ad.x += hj[j] * w2.x; ad.y += hj[j] * w2.y; ad.z += hj[j] * w2.z; ad.w += hj[j] * w2.w;
    }
    #pragma unroll
    for (int off = 16; off; off >>= 1) {
        as.x += __shfl_xor_sync(0xffffffffu, as.x, off);
        as.y += __shfl_xor_sync(0xffffffffu, as.y, off);
        as.z += __shfl_xor_sync(0xffffffffu, as.z, off);
        as.w += __shfl_xor_sync(0xffffffffu, as.w, off);
        ad.x += __shfl_xor_sync(0xffffffffu, ad.x, off);
        ad.y += __shfl_xor_sync(0xffffffffu, ad.y, off);
        ad.z += __shfl_xor_sync(0xffffffffu, ad.z, off);
        ad.w += __shfl_xor_sync(0xffffffffu, ad.w, off);
    }
    if (lane == 0) {
        float4* pv = reinterpret_cast<float4*>(d_p + (size_t)gw * 8);
        pv[0] = as; pv[1] = ad;
    }
}

// ---------------- per-edge output: out[e] = p_src[row] + p_dst[col] + bc ----------------
__global__ void k_edge(const int* __restrict__ ei, const float* __restrict__ bc,
                       float* __restrict__ out) {
    int e = blockIdx.x * blockDim.x + threadIdx.x;
    if (e >= EE) return;
    int r = ei[e], c = ei[EE + e];
    const float4* pv = reinterpret_cast<const float4*>(d_p);
    float4 a = pv[r * 2];
    float4 b = pv[c * 2 + 1];
    float4 bc4 = *reinterpret_cast<const float4*>(bc);
    reinterpret_cast<float4*>(out)[e] =
        make_float4(a.x + b.x + bc4.x, a.y + b.y + bc4.y,
                    a.z + b.z + bc4.z, a.w + b.w + bc4.w);
}

// ---------------- launcher ----------------
extern "C" void kernel_launch(void* const* d_in, const int* in_sizes, int n_in,
                              void* d_out, int out_size) {
    const float* x   = (const float*)d_in[0];
    const int*   ei  = (const int*)  d_in[1];
    const float* W1  = (const float*)d_in[2];
    const float* al1 = (const float*)d_in[3];
    const float* ar1 = (const float*)d_in[4];
    const float* b1  = (const float*)d_in[5];
    const float* W2  = (const float*)d_in[6];
    const float* al2 = (const float*)d_in[7];
    const float* ar2 = (const float*)d_in[8];
    const float* b2  = (const float*)d_in[9];
    const float* Wc  = (const float*)d_in[10];
    const float* bc  = (const float*)d_in[11];
    float* out = (float*)d_out;

    static cudaStream_t s2 = nullptr;
    static cudaEvent_t evFork = nullptr, evJoin = nullptr;
    if (!s2) {
        cudaStreamCreateWithFlags(&s2, cudaStreamNonBlocking);
        cudaEventCreateWithFlags(&evFork, cudaEventDisableTiming);
        cudaEventCreateWithFlags(&evJoin, cudaEventDisableTiming);
    }

    void* fillPtr = nullptr;
    cudaGetSymbolAddress(&fillPtr, d_fill);

    // fork: bucket build on s2, concurrent with GEMM-1 on the main stream
    cudaEventRecord(evFork, 0);
    cudaStreamWaitEvent(s2, evFork, 0);

    cudaMemsetAsync(fillPtr, 0, NN * sizeof(int), s2);
    k_place1<<<(EE + 255) / 256, 256, 0, s2>>>(ei);                    // kernel #1
    k_place2<<<(NN + 255) / 256, 256, 0, s2>>>();                      // kernel #2
    k_gemm<<<(NN + 127) / 128, 256>>>(x, W1, al1, ar1, 0, 0);          // kernel #3

    cudaEventRecord(evJoin, s2);
    cudaStreamWaitEvent(0, evJoin, 0);

    k_attn<<<(NN * 32 + 255) / 256, 256>>>(0, b1, 1, 0, nullptr);      // kernel #4 <- profiled
    k_gemm<<<(NN + 127) / 128, 256>>>(nullptr, W2, al2, ar2, 1, 1);
    k_attn<<<(NN * 32 + 255) / 256, 256>>>(1, b2, 0, 1, Wc);
    k_edge<<<(EE + 255) / 256, 256>>>(ei, bc, out);
}

// round 9
// speedup vs baseline: 1.0098x; 1.0098x over previous
#include <cuda_runtime.h>
#include <cuda_fp16.h>

#define NN   50000
#define EE   800000
#define HID  128
#define BK   64          // padded bucket width (max degree incl. self-loop ~40)

// ---------------- device scratch (no allocations allowed) ----------------
__device__ float  d_h1[NN * HID];    // x @ W1 (fp32)
__device__ float  d_t1[NN * HID];    // relu(layer1 out)
__device__ float  d_h2[NN * HID];    // t1 @ W2 (fp32)
__device__ __half d_hh[NN * HID];    // fp16 gather copy of current layer's h
__device__ float  d_al[NN];
__device__ float  d_ar[NN];
__device__ int    d_srcPad[NN * BK]; // padded per-dst source buckets
__device__ int    d_fill[NN];        // per-dst degree (incl. self-loop)
__device__ float  d_p[NN * 8];       // per-node [p_src(4), p_dst(4)]

// ---------------- packed f32x2 helpers (sm_100+ FFMA2 path) ----------------
__device__ __forceinline__ unsigned long long pack2(float lo, float hi) {
    unsigned long long r;
    asm("mov.b64 %0,{%1,%2};" : "=l"(r) : "f"(lo), "f"(hi));
    return r;
}
__device__ __forceinline__ unsigned long long fma2(unsigned long long a,
                                                   unsigned long long b,
                                                   unsigned long long c) {
    unsigned long long d;
    asm("fma.rn.f32x2 %0,%1,%2,%3;" : "=l"(d) : "l"(a), "l"(b), "l"(c));
    return d;
}
__device__ __forceinline__ void unpack2(unsigned long long v, float& lo, float& hi) {
    asm("mov.b64 {%0,%1},%2;" : "=f"(lo), "=f"(hi) : "l"(v));
}

// convert uint4 (8 fp16) -> 8 fp32
__device__ __forceinline__ void cvt8(uint4 r, float* o) {
    float2 a = __half22float2(*reinterpret_cast<__half2*>(&r.x));
    float2 b = __half22float2(*reinterpret_cast<__half2*>(&r.y));
    float2 c = __half22float2(*reinterpret_cast<__half2*>(&r.z));
    float2 d = __half22float2(*reinterpret_cast<__half2*>(&r.w));
    o[0] = a.x; o[1] = a.y; o[2] = b.x; o[3] = b.y;
    o[4] = c.x; o[5] = c.y; o[6] = d.x; o[7] = d.y;
}

// ---------------- scan-free CSR: padded bucket scatter ----------------
__global__ void k_place1(const int* __restrict__ ei) {
    int e = blockIdx.x * blockDim.x + threadIdx.x;
    if (e >= EE) return;
    int c = ei[EE + e];
    int pos = atomicAdd(&d_fill[c], 1);
    if (pos < BK) d_srcPad[c * BK + pos] = ei[e];
}
__global__ void k_place2() {
    int n = blockIdx.x * blockDim.x + threadIdx.x;
    if (n >= NN) return;
    int pos = atomicAdd(&d_fill[n], 1);
    if (pos < BK) d_srcPad[n * BK + pos] = n;
}

// ---------------- GEMM: C[M,128] = A[M,128] @ B[128,128], fp32 via FFMA2 ----------------
__global__ void __launch_bounds__(256) k_gemm(const float* __restrict__ Aext,
                                              const float* __restrict__ B,
                                              const float* __restrict__ attl,
                                              const float* __restrict__ attr,
                                              int selA, int selC) {
    const float* A = selA ? d_t1 : Aext;
    float* C = selC ? d_h2 : d_h1;

    __shared__ float As[16][132];
    __shared__ float Bs[16][128];

    int tid = threadIdx.x;
    int tr = tid >> 4, tc = tid & 15;
    int mBase = blockIdx.x * 128;
    int c0 = tc * 4;
    int c1 = 64 + tc * 4;

    unsigned long long acc[8][4];
    unsigned long long z = pack2(0.f, 0.f);
    #pragma unroll
    for (int i = 0; i < 8; i++)
        #pragma unroll
        for (int p = 0; p < 4; p++) acc[i][p] = z;

    for (int kc = 0; kc < 128; kc += 16) {
        #pragma unroll
        for (int l = 0; l < 2; l++) {
            int f = tid + l * 256;
            int r = f >> 2, cg = (f & 3) << 2;
            float4 v = make_float4(0.f, 0.f, 0.f, 0.f);
            int gr = mBase + r;
            if (gr < NN) v = *reinterpret_cast<const float4*>(A + (size_t)gr * HID + kc + cg);
            As[cg + 0][r] = v.x; As[cg + 1][r] = v.y; As[cg + 2][r] = v.z; As[cg + 3][r] = v.w;
            int k = f >> 5, n4 = (f & 31) << 2;
            *reinterpret_cast<float4*>(&Bs[k][n4]) =
                *reinterpret_cast<const float4*>(B + (size_t)(kc + k) * HID + n4);
        }
        __syncthreads();
        #pragma unroll
        for (int kk = 0; kk < 16; kk++) {
            float4 a0 = *reinterpret_cast<const float4*>(&As[kk][tr * 8]);
            float4 a1 = *reinterpret_cast<const float4*>(&As[kk][tr * 8 + 4]);
            float4 b0 = *reinterpret_cast<const float4*>(&Bs[kk][c0]);
            float4 b1 = *reinterpret_cast<const float4*>(&Bs[kk][c1]);
            unsigned long long pb[4];
            pb[0] = pack2(b0.x, b0.y); pb[1] = pack2(b0.z, b0.w);
            pb[2] = pack2(b1.x, b1.y); pb[3] = pack2(b1.z, b1.w);
            float av[8] = {a0.x, a0.y, a0.z, a0.w, a1.x, a1.y, a1.z, a1.w};
            #pragma unroll
            for (int i = 0; i < 8; i++) {
                unsigned long long ad = pack2(av[i], av[i]);
                #pragma unroll
                for (int p = 0; p < 4; p++) acc[i][p] = fma2(ad, pb[p], acc[i][p]);
            }
        }
        __syncthreads();
    }

    float alv[8], arv[8];
    #pragma unroll
    for (int j = 0; j < 4; j++) {
        alv[j]     = attl[c0 + j]; arv[j]     = attr[c0 + j];
        alv[4 + j] = attl[c1 + j]; arv[4 + j] = attr[c1 + j];
    }

    #pragma unroll
    for (int i = 0; i < 8; i++) {
        int gr = mBase + tr * 8 + i;
        float cv[8];
        unpack2(acc[i][0], cv[0], cv[1]); unpack2(acc[i][1], cv[2], cv[3]);
        unpack2(acc[i][2], cv[4], cv[5]); unpack2(acc[i][3], cv[6], cv[7]);
        float pl = 0.f, pr = 0.f;
        #pragma unroll
        for (int j = 0; j < 8; j++) { pl += cv[j] * alv[j]; pr += cv[j] * arv[j]; }
        #pragma unroll
        for (int off = 8; off; off >>= 1) {
            pl += __shfl_xor_sync(0xffffffffu, pl, off);
            pr += __shfl_xor_sync(0xffffffffu, pr, off);
        }
        if (gr < NN) {
            *reinterpret_cast<float4*>(C + (size_t)gr * HID + c0) =
                make_float4(cv[0], cv[1], cv[2], cv[3]);
            *reinterpret_cast<float4*>(C + (size_t)gr * HID + c1) =
                make_float4(cv[4], cv[5], cv[6], cv[7]);
            __half2 p01 = __floats2half2_rn(cv[0], cv[1]);
            __half2 p23 = __floats2half2_rn(cv[2], cv[3]);
            __half2 p45 = __floats2half2_rn(cv[4], cv[5]);
            __half2 p67 = __floats2half2_rn(cv[6], cv[7]);
            uint2 u0, u1;
            u0.x = *reinterpret_cast<unsigned*>(&p01); u0.y = *reinterpret_cast<unsigned*>(&p23);
            u1.x = *reinterpret_cast<unsigned*>(&p45); u1.y = *reinterpret_cast<unsigned*>(&p67);
            *reinterpret_cast<uint2*>(d_hh + (size_t)gr * HID + c0) = u0;
            *reinterpret_cast<uint2*>(d_hh + (size_t)gr * HID + c1) = u1;
            if (tc == 0) { d_al[gr] = pl; d_ar[gr] = pr; }
        }
    }
}

// ---------------- fused SuperGAT attention (no-max softmax, 16-lane x 2-edge) ----------------
// warp = 1 dst node; lanes split into 2 groups of 16; group g processes edge i+g.
// Each lane owns 8 features (f*8 .. f*8+7).
__global__ void k_attn(int selH, const float* __restrict__ bias, int doRelu,
                       int doProj, const float* __restrict__ Wc) {
    int gw = (blockIdx.x * blockDim.x + threadIdx.x) >> 5;
    if (gw >= NN) return;
    int lane = threadIdx.x & 31;
    int g = lane >> 4, f = lane & 15;
    const float* h = selH ? d_h2 : d_h1;

    float hd[8];
    {
        const float4* hr = reinterpret_cast<const float4*>(h + (size_t)gw * HID + f * 8);
        float4 x0 = hr[0], x1 = hr[1];
        hd[0] = x0.x; hd[1] = x0.y; hd[2] = x0.z; hd[3] = x0.w;
        hd[4] = x1.x; hd[5] = x1.y; hd[6] = x1.z; hd[7] = x1.w;
    }
    float ard = d_ar[gw];
    const int* sp = d_srcPad + gw * BK;
    int deg = d_fill[gw];
    if (deg > BK) deg = BK;

    float acc[8] = {0.f, 0.f, 0.f, 0.f, 0.f, 0.f, 0.f, 0.f};
    float ss = 0.f;

    int i = 0;
    // main: 4 edges per iteration (2 warp-steps)
    for (; i + 4 <= deg; i += 4) {
        int4 sv = *reinterpret_cast<const int4*>(sp + i);
        int sA = g ? sv.y : sv.x;
        int sB = g ? sv.w : sv.z;
        float alA = d_al[sA];
        float alB = d_al[sB];
        uint4 rA = *reinterpret_cast<const uint4*>(d_hh + (size_t)sA * HID + f * 8);
        uint4 rB = *reinterpret_cast<const uint4*>(d_hh + (size_t)sB * HID + f * 8);
        float hsA[8], hsB[8];
        cvt8(rA, hsA); cvt8(rB, hsB);
        float pA = 0.f, pB = 0.f;
        #pragma unroll
        for (int k = 0; k < 8; k++) { pA += hd[k] * hsA[k]; pB += hd[k] * hsB[k]; }
        #pragma unroll
        for (int off = 8; off; off >>= 1) {
            pA += __shfl_xor_sync(0xffffffffu, pA, off);
            pB += __shfl_xor_sync(0xffffffffu, pB, off);
        }
        float aA = (alA + ard) * (1.0f / (1.0f + __expf(-pA)));
        float aB = (alB + ard) * (1.0f / (1.0f + __expf(-pB)));
        float eA = __expf(aA);
        float eB = __expf(aB);
        #pragma unroll
        for (int k = 0; k < 8; k++) acc[k] += eA * hsA[k] + eB * hsB[k];
        ss += eA + eB;
    }
    // tail: 1-3 edges, 2 per step with predication
    for (; i < deg; i += 2) {
        int e0 = i + g;
        bool valid = e0 < deg;
        int s0 = sp[valid ? e0 : 0];
        float al0 = d_al[s0];
        uint4 r0 = *reinterpret_cast<const uint4*>(d_hh + (size_t)s0 * HID + f * 8);
        float hs0[8];
        cvt8(r0, hs0);
        float p0 = 0.f;
        #pragma unroll
        for (int k = 0; k < 8; k++) p0 += hd[k] * hs0[k];
        #pragma unroll
        for (int off = 8; off; off >>= 1) p0 += __shfl_xor_sync(0xffffffffu, p0, off);
        float a0 = (al0 + ard) * (1.0f / (1.0f + __expf(-p0)));
        float e_w = valid ? __expf(a0) : 0.f;
        #pragma unroll
        for (int k = 0; k < 8; k++) acc[k] += e_w * hs0[k];
        ss += e_w;
    }

    // combine the two 16-lane groups
    #pragma unroll
    for (int k = 0; k < 8; k++) acc[k] += __shfl_xor_sync(0xffffffffu, acc[k], 16);
    ss += __shfl_xor_sync(0xffffffffu, ss, 16);

    float inv = 1.0f / (ss + 1e-16f);
    float o[8];
    {
        const float4* bb = reinterpret_cast<const float4*>(bias + f * 8);
        float4 b0 = bb[0], b1 = bb[1];
        float bv[8] = {b0.x, b0.y, b0.z, b0.w, b1.x, b1.y, b1.z, b1.w};
        #pragma unroll
        for (int k = 0; k < 8; k++) {
            o[k] = acc[k] * inv + bv[k];
            if (doRelu) o[k] = fmaxf(o[k], 0.f);
        }
    }

    if (!doProj) {
        // lane (g,f) stores floats [f*8 + g*4, +4)
        float4 st = g ? make_float4(o[4], o[5], o[6], o[7])
                      : make_float4(o[0], o[1], o[2], o[3]);
        *reinterpret_cast<float4*>(d_t1 + (size_t)gw * HID + f * 8 + g * 4) = st;
        return;
    }

    // fused classifier partials: group 0 -> Wc rows 0..127 (p_src),
    //                            group 1 -> Wc rows 128..255 (p_dst)
    const float* wb = Wc + (g ? 128 * 4 : 0);
    float4 vv = make_float4(0.f, 0.f, 0.f, 0.f);
    #pragma unroll
    for (int k = 0; k < 8; k++) {
        float4 w = *reinterpret_cast<const float4*>(wb + (f * 8 + k) * 4);
        vv.x += o[k] * w.x; vv.y += o[k] * w.y; vv.z += o[k] * w.z; vv.w += o[k] * w.w;
    }
    #pragma unroll
    for (int off = 8; off; off >>= 1) {
        vv.x += __shfl_xor_sync(0xffffffffu, vv.x, off);
        vv.y += __shfl_xor_sync(0xffffffffu, vv.y, off);
        vv.z += __shfl_xor_sync(0xffffffffu, vv.z, off);
        vv.w += __shfl_xor_sync(0xffffffffu, vv.w, off);
    }
    if (f == 0)
        *reinterpret_cast<float4*>(d_p + (size_t)gw * 8 + g * 4) = vv;
}

// ---------------- per-edge output: out[e] = p_src[row] + p_dst[col] + bc ----------------
__global__ void k_edge(const int* __restrict__ ei, const float* __restrict__ bc,
                       float* __restrict__ out) {
    int e = blockIdx.x * blockDim.x + threadIdx.x;
    if (e >= EE) return;
    int r = ei[e], c = ei[EE + e];
    const float4* pv = reinterpret_cast<const float4*>(d_p);
    float4 a = pv[r * 2];
    float4 b = pv[c * 2 + 1];
    float4 bc4 = *reinterpret_cast<const float4*>(bc);
    reinterpret_cast<float4*>(out)[e] =
        make_float4(a.x + b.x + bc4.x, a.y + b.y + bc4.y,
                    a.z + b.z + bc4.z, a.w + b.w + bc4.w);
}

// ---------------- launcher ----------------
extern "C" void kernel_launch(void* const* d_in, const int* in_sizes, int n_in,
                              void* d_out, int out_size) {
    const float* x   = (const float*)d_in[0];
    const int*   ei  = (const int*)  d_in[1];
    const float* W1  = (const float*)d_in[2];
    const float* al1 = (const float*)d_in[3];
    const float* ar1 = (const float*)d_in[4];
    const float* b1  = (const float*)d_in[5];
    const float* W2  = (const float*)d_in[6];
    const float* al2 = (const float*)d_in[7];
    const float* ar2 = (const float*)d_in[8];
    const float* b2  = (const float*)d_in[9];
    const float* Wc  = (const float*)d_in[10];
    const float* bc  = (const float*)d_in[11];
    float* out = (float*)d_out;

    static cudaStream_t s2 = nullptr;
    static cudaEvent_t evFork = nullptr, evJoin = nullptr;
    if (!s2) {
        cudaStreamCreateWithFlags(&s2, cudaStreamNonBlocking);
        cudaEventCreateWithFlags(&evFork, cudaEventDisableTiming);
        cudaEventCreateWithFlags(&evJoin, cudaEventDisableTiming);
    }

    void* fillPtr = nullptr;
    cudaGetSymbolAddress(&fillPtr, d_fill);

    // fork: bucket build on s2, concurrent with GEMM-1 on the main stream
    cudaEventRecord(evFork, 0);
    cudaStreamWaitEvent(s2, evFork, 0);

    cudaMemsetAsync(fillPtr, 0, NN * sizeof(int), s2);
    k_place1<<<(EE + 255) / 256, 256, 0, s2>>>(ei);                    // kernel #1
    k_place2<<<(NN + 255) / 256, 256, 0, s2>>>();                      // kernel #2
    k_gemm<<<(NN + 127) / 128, 256>>>(x, W1, al1, ar1, 0, 0);          // kernel #3

    cudaEventRecord(evJoin, s2);
    cudaStreamWaitEvent(0, evJoin, 0);

    k_attn<<<(NN * 32 + 255) / 256, 256>>>(0, b1, 1, 0, nullptr);      // kernel #4 <- profiled
    k_gemm<<<(NN + 127) / 128, 256>>>(nullptr, W2, al2, ar2, 1, 1);
    k_attn<<<(NN * 32 + 255) / 256, 256>>>(1, b2, 0, 1, Wc);
    k_edge<<<(EE + 255) / 256, 256>>>(ei, bc, out);
}